// round 12
// baseline (speedup 1.0000x reference)
#include <cuda_runtime.h>
#include <cuda_bf16.h>
#include <cstdint>
#include <math.h>

#define EPSY (1.0f/137.0f)
#define NEGINF (-3.402823466e38f)

// ================= helpers ===================================================
__device__ __forceinline__ uint32_t smem_u32(const void* p) {
    uint32_t a;
    asm("{ .reg .u64 t; cvta.to.shared.u64 t, %1; cvt.u32.u64 %0, t; }"
        : "=r"(a) : "l"(p));
    return a;
}
__device__ __forceinline__ void cp16(uint32_t s, const void* g) {
    asm volatile("cp.async.cg.shared.global [%0], [%1], 16;" :: "r"(s), "l"(g));
}
#define CP_COMMIT() asm volatile("cp.async.commit_group;" ::: "memory")
#define CP_WAIT1()  asm volatile("cp.async.wait_group 1;" ::: "memory")
#define CP_WAIT0()  asm volatile("cp.async.wait_group 0;" ::: "memory")

__device__ __forceinline__ void ldsm4(uint32_t* r, uint32_t addr) {
    asm volatile("ldmatrix.sync.aligned.m8n8.x4.shared.b16 {%0,%1,%2,%3}, [%4];"
        : "=r"(r[0]), "=r"(r[1]), "=r"(r[2]), "=r"(r[3]) : "r"(addr));
}
__device__ __forceinline__ void ldsm4t(uint32_t* r, uint32_t addr) {
    asm volatile("ldmatrix.sync.aligned.m8n8.x4.trans.shared.b16 {%0,%1,%2,%3}, [%4];"
        : "=r"(r[0]), "=r"(r[1]), "=r"(r[2]), "=r"(r[3]) : "r"(addr));
}
__device__ __forceinline__ void mma16816(float* d, const uint32_t* a, const uint32_t* b) {
    asm volatile(
        "mma.sync.aligned.m16n8k16.row.col.f32.bf16.bf16.f32 "
        "{%0,%1,%2,%3}, {%4,%5,%6,%7}, {%8,%9}, {%0,%1,%2,%3};"
        : "+f"(d[0]), "+f"(d[1]), "+f"(d[2]), "+f"(d[3])
        : "r"(a[0]), "r"(a[1]), "r"(a[2]), "r"(a[3]), "r"(b[0]), "r"(b[1]));
}
__device__ __forceinline__ uint32_t packbf(float a, float b) {
    __nv_bfloat162 p;
    p.x = __float2bfloat16(a);
    p.y = __float2bfloat16(b);
    return *(uint32_t*)&p;
}

// ================= scratch (static device memory) ===========================
__device__ float g_xn[4096];
__device__ float g_an[4096];
__device__ float g_anp[4096 * 12];
__device__ float g_wn1[2304];
__device__ float g_wn2[768];
__device__ __nv_bfloat16 g_qkvh[4096 * 2304], g_qkvl[4096 * 2304];
__device__ __nv_bfloat16 g_xhi[4096 * 768], g_xlo[4096 * 768];
__device__ __nv_bfloat16 g_ahi[4096 * 768], g_alo[4096 * 768];
__device__ __nv_bfloat16 g_w1hi[2304 * 768], g_w1lo[2304 * 768];
__device__ __nv_bfloat16 g_w2hi[768 * 768], g_w2lo[768 * 768];

// ================= prep kernels =============================================
__global__ void split_norm_k(const float* __restrict__ X, __nv_bfloat16* __restrict__ H,
                             __nv_bfloat16* __restrict__ L, float* __restrict__ nrm,
                             int M, int K) {
    int row = blockIdx.x * 8 + (threadIdx.x >> 5);
    int lane = threadIdx.x & 31;
    if (row >= M) return;
    const float* p = X + (long)row * K;
    float s = 0.f;
    for (int k = lane; k < K; k += 32) {
        float v = p[k];
        s = fmaf(v, v, s);
        __nv_bfloat16 hb = __float2bfloat16(v);
        H[(long)row * K + k] = hb;
        L[(long)row * K + k] = __float2bfloat16(v - __bfloat162float(hb));
    }
    #pragma unroll
    for (int o = 16; o; o >>= 1) s += __shfl_xor_sync(0xffffffffu, s, o);
    if (!lane) nrm[row] = s;
}

__global__ void colnorm_k(const float* __restrict__ W, float* __restrict__ o, int K, int N) {
    int n = blockIdx.x * blockDim.x + threadIdx.x;
    if (n >= N) return;
    float s = 0.f;
    for (int k = 0; k < K; k++) { float v = W[(long)k * N + n]; s = fmaf(v, v, s); }
    o[n] = s;
}

__global__ void anred_k(const float* __restrict__ part, float* __restrict__ o) {
    int r = blockIdx.x * 256 + threadIdx.x;
    float s = 0.f;
    #pragma unroll
    for (int h = 0; h < 12; h++) s += part[r * 12 + h];
    o[r] = s;
}

__global__ void wtrans_split_k(const float* __restrict__ W, __nv_bfloat16* __restrict__ Th,
                               __nv_bfloat16* __restrict__ Tl, int K, int N) {
    __shared__ float t[32][33];
    int n0 = blockIdx.x * 32, k0 = blockIdx.y * 32;
    int tx = threadIdx.x, ty = threadIdx.y;  // (32, 8)
    #pragma unroll
    for (int j = 0; j < 32; j += 8)
        t[ty + j][tx] = W[(long)(k0 + ty + j) * N + n0 + tx];
    __syncthreads();
    #pragma unroll
    for (int j = 0; j < 32; j += 8) {
        float v = t[tx][ty + j];
        __nv_bfloat16 hb = __float2bfloat16(v);
        Th[(long)(n0 + ty + j) * K + k0 + tx] = hb;
        Tl[(long)(n0 + ty + j) * K + k0 + tx] = __float2bfloat16(v - __bfloat162float(hb));
    }
}

// ================= HMMA Yat-GEMM (BK=32, 2 CTAs/SM) =========================
#define BK 32
#define STR 80                    // 32 bf16 = 64B + 16B pad
#define MAT_BYTES (128 * STR)     // 10240
#define BUF_BYTES (4 * MAT_BYTES) // 40960
#define GEMM_SMEM (2 * BUF_BYTES) // 81920

__global__ __launch_bounds__(256, 2)
void gemm_mma_k(const __nv_bfloat16* __restrict__ Ah, const __nv_bfloat16* __restrict__ Al,
                const __nv_bfloat16* __restrict__ Bh, const __nv_bfloat16* __restrict__ Bl,
                const float* __restrict__ bias, const float* __restrict__ rn,
                const float* __restrict__ cn, const float* __restrict__ alphaPtr,
                float* __restrict__ Cout,
                __nv_bfloat16* __restrict__ Ohi, __nv_bfloat16* __restrict__ Olo,
                int M, int N, int K, float baseF) {
    extern __shared__ char smc[];
    uint32_t sb = smem_u32(smc);
    int tid = threadIdx.x, wid = tid >> 5, lane = tid & 31;
    int M0 = blockIdx.y * 128, N0 = blockIdx.x * 128;
    int wm = wid & 1, wn = wid >> 1;

    float acc[4][4][4];
    #pragma unroll
    for (int i = 0; i < 4; i++)
        #pragma unroll
        for (int j = 0; j < 4; j++)
            #pragma unroll
            for (int u = 0; u < 4; u++) acc[i][j][u] = 0.f;

    const int NCH = K / BK;  // 24

    auto load_chunk = [&](int c, int buf) {
        int k0 = c * BK;
        uint32_t base = sb + buf * BUF_BYTES;
        #pragma unroll
        for (int l = 0; l < 2; l++) {
            int f = tid + l * 256;      // 0..511
            int row = f >> 2, seg = f & 3;
            uint32_t so = row * STR + seg * 16;
            long ga = (long)(M0 + row) * K + k0 + seg * 8;
            long gb = (long)(N0 + row) * K + k0 + seg * 8;
            cp16(base + so,                 Ah + ga);
            cp16(base + MAT_BYTES + so,     Al + ga);
            cp16(base + 2 * MAT_BYTES + so, Bh + gb);
            cp16(base + 3 * MAT_BYTES + so, Bl + gb);
        }
    };

    load_chunk(0, 0); CP_COMMIT();
    load_chunk(1, 1); CP_COMMIT();

    int gq = lane >> 3, rq = lane & 7;
    int arow = wm * 64 + (gq & 1) * 8 + rq;
    int acol8 = (gq >> 1) * 8;
    int brow = wn * 32 + (gq >> 1) * 8 + rq;
    int bcol8 = (gq & 1) * 8;

    for (int c = 0; c < NCH; c++) {
        if (c + 1 < NCH) { CP_WAIT1(); } else { CP_WAIT0(); }
        __syncthreads();
        uint32_t base = sb + (c & 1) * BUF_BYTES;
        uint32_t bAh = base, bAl = base + MAT_BYTES;
        uint32_t bBh = base + 2 * MAT_BYTES, bBl = base + 3 * MAT_BYTES;

        #pragma unroll
        for (int ks = 0; ks < BK / 16; ks++) {
            int kc = ks * 16;
            uint32_t ah[4][4], al[4][4], bh[4][2], bl[4][2];
            #pragma unroll
            for (int i = 0; i < 4; i++) {
                uint32_t off = (uint32_t)((arow + i * 16) * STR + (kc + acol8) * 2);
                ldsm4(ah[i], bAh + off);
                ldsm4(al[i], bAl + off);
            }
            #pragma unroll
            for (int jp = 0; jp < 2; jp++) {
                uint32_t off = (uint32_t)((brow + jp * 16) * STR + (kc + bcol8) * 2);
                uint32_t r[4];
                ldsm4(r, bBh + off);
                bh[jp * 2][0] = r[0]; bh[jp * 2][1] = r[1];
                bh[jp * 2 + 1][0] = r[2]; bh[jp * 2 + 1][1] = r[3];
                ldsm4(r, bBl + off);
                bl[jp * 2][0] = r[0]; bl[jp * 2][1] = r[1];
                bl[jp * 2 + 1][0] = r[2]; bl[jp * 2 + 1][1] = r[3];
            }
            #pragma unroll
            for (int i = 0; i < 4; i++)
                #pragma unroll
                for (int j = 0; j < 4; j++) {
                    mma16816(acc[i][j], ah[i], bh[j]);
                    mma16816(acc[i][j], ah[i], bl[j]);
                    mma16816(acc[i][j], al[i], bh[j]);
                }
        }
        if (c + 2 < NCH) {
            __syncthreads();
            load_chunk(c + 2, c & 1);
            CP_COMMIT();
        }
    }

    float alpha = __ldg(alphaPtr);
    float scaleF = powf(sqrtf(baseF) / logf(1.0f + baseF), alpha);
    int tq = lane >> 2, tr = lane & 3;
    #pragma unroll
    for (int i = 0; i < 4; i++) {
        int m0 = M0 + wm * 64 + i * 16 + tq;
        float rn0 = __ldg(&rn[m0]);
        float rn1 = __ldg(&rn[m0 + 8]);
        #pragma unroll
        for (int j = 0; j < 4; j++) {
            int n0 = N0 + wn * 32 + j * 8 + tr * 2;
            float cn0 = __ldg(&cn[n0]), cn1 = __ldg(&cn[n0 + 1]);
            float bb0 = __ldg(&bias[n0]), bb1 = __ldg(&bias[n0 + 1]);
            float c0 = acc[i][j][0], c1 = acc[i][j][1];
            float c2 = acc[i][j][2], c3 = acc[i][j][3];
            float2 r0, r1;
            r0.x = (c0 * c0 / (rn0 + cn0 - 2.f * c0 + EPSY) + bb0) * scaleF;
            r0.y = (c1 * c1 / (rn0 + cn1 - 2.f * c1 + EPSY) + bb1) * scaleF;
            r1.x = (c2 * c2 / (rn1 + cn0 - 2.f * c2 + EPSY) + bb0) * scaleF;
            r1.y = (c3 * c3 / (rn1 + cn1 - 2.f * c3 + EPSY) + bb1) * scaleF;
            if (Cout) {
                *(float2*)&Cout[(long)m0 * N + n0] = r0;
                *(float2*)&Cout[(long)(m0 + 8) * N + n0] = r1;
            }
            if (Ohi) {
                uint32_t h0 = packbf(r0.x, r0.y);
                uint32_t h1 = packbf(r1.x, r1.y);
                *(uint32_t*)&Ohi[(long)m0 * N + n0] = h0;
                *(uint32_t*)&Ohi[(long)(m0 + 8) * N + n0] = h1;
                __nv_bfloat162 hh0 = *(__nv_bfloat162*)&h0;
                __nv_bfloat162 hh1 = *(__nv_bfloat162*)&h1;
                uint32_t l0 = packbf(r0.x - __bfloat162float(hh0.x),
                                     r0.y - __bfloat162float(hh0.y));
                uint32_t l1 = packbf(r1.x - __bfloat162float(hh1.x),
                                     r1.y - __bfloat162float(hh1.y));
                *(uint32_t*)&Olo[(long)m0 * N + n0] = l0;
                *(uint32_t*)&Olo[(long)(m0 + 8) * N + n0] = l1;
            }
        }
    }
}

// ================= HMMA Yat flash attention (KV tile 64, 2 CTAs/SM) =========
#define ASTR 144
#define AMATQ (128 * ASTR)            // 18432
#define AMATK (64 * ASTR)             // 9216
#define AQOFF 0                       // Qh, Ql
#define AKV0 (2 * AMATQ)              // 36864
#define AKVSZ (4 * AMATK)             // 36864 per buffer (Kh,Kl,Vh,Vl)
#define AKN (AKV0 + 2 * AKVSZ)        // 110592
#define ATTN_SMEM (AKN + 2 * 256)     // 111104

__global__ __launch_bounds__(256, 2)
void attn_mma_k(const __nv_bfloat16* __restrict__ qh,
                const __nv_bfloat16* __restrict__ ql,
                __nv_bfloat16* __restrict__ ohi, __nv_bfloat16* __restrict__ olo,
                float* __restrict__ anp) {
    extern __shared__ char smc[];
    uint32_t sb = smem_u32(smc);
    int tid = threadIdx.x, wq = tid >> 5, lane = tid & 31;
    int h = blockIdx.x, b = blockIdx.y;
    int qt = 7 - blockIdx.z;          // longest CTAs first
    int q0 = qt * 128;
    const int T = 1024, C3 = 2304;
    long rbase = (long)b * T * C3;
    int qcol = h * 64, kcol = 768 + h * 64, vcol = 1536 + h * 64;
    const int NKT = 2 * (qt + 1);     // 64-row key tiles

    auto loadQ = [&]() {
        #pragma unroll
        for (int l = 0; l < 4; l++) {
            int f = tid + l * 256;
            int row = f >> 3, seg = f & 7;
            long g = rbase + (long)(q0 + row) * C3 + qcol + seg * 8;
            uint32_t so = row * ASTR + seg * 16;
            cp16(sb + AQOFF + so, qh + g);
            cp16(sb + AQOFF + AMATQ + so, ql + g);
        }
    };
    auto loadKV = [&](int kt, int buf) {
        int k0 = kt * 64;
        uint32_t base = sb + AKV0 + buf * AKVSZ;
        #pragma unroll
        for (int l = 0; l < 2; l++) {
            int f = tid + l * 256;      // 0..511
            int row = f >> 3, seg = f & 7;
            uint32_t so = row * ASTR + seg * 16;
            long gk = rbase + (long)(k0 + row) * C3 + kcol + seg * 8;
            long gv = rbase + (long)(k0 + row) * C3 + vcol + seg * 8;
            cp16(base + so,             qh + gk);
            cp16(base + AMATK + so,     ql + gk);
            cp16(base + 2 * AMATK + so, qh + gv);
            cp16(base + 3 * AMATK + so, ql + gv);
        }
    };

    loadQ(); loadKV(0, 0); CP_COMMIT();
    if (NKT > 1) { loadKV(1, 1); CP_COMMIT(); CP_WAIT1(); } else { CP_WAIT0(); }
    __syncthreads();

    int gq = lane >> 3, rq = lane & 7;
    int arow = wq * 16 + (gq & 1) * 8 + rq;
    int acol8 = (gq >> 1) * 8;
    uint32_t qfh[4][4], qfl[4][4];
    #pragma unroll
    for (int s = 0; s < 4; s++) {
        uint32_t off = (uint32_t)(arow * ASTR + (s * 16 + acol8) * 2);
        ldsm4(qfh[s], sb + AQOFF + off);
        ldsm4(qfl[s], sb + AQOFF + AMATQ + off);
    }
    float qn0 = 0.f, qn1 = 0.f;
    #pragma unroll
    for (int s = 0; s < 4; s++)
        #pragma unroll
        for (int r = 0; r < 4; r++) {
            __nv_bfloat162 hh = *(__nv_bfloat162*)&qfh[s][r];
            __nv_bfloat162 ll = *(__nv_bfloat162*)&qfl[s][r];
            float v0 = __bfloat162float(hh.x) + __bfloat162float(ll.x);
            float v1 = __bfloat162float(hh.y) + __bfloat162float(ll.y);
            float ss = v0 * v0 + v1 * v1;
            if ((r & 1) == 0) qn0 += ss; else qn1 += ss;
        }
    qn0 += __shfl_xor_sync(0xffffffffu, qn0, 1);
    qn0 += __shfl_xor_sync(0xffffffffu, qn0, 2);
    qn1 += __shfl_xor_sync(0xffffffffu, qn1, 1);
    qn1 += __shfl_xor_sync(0xffffffffu, qn1, 2);

    int tq = lane >> 2, t = lane & 3;
    int gr0 = q0 + wq * 16 + tq, gr1 = gr0 + 8;
    float m0r = NEGINF, m1r = NEGINF, l0r = 0.f, l1r = 0.f;
    float O[8][4];
    #pragma unroll
    for (int j = 0; j < 8; j++)
        #pragma unroll
        for (int u = 0; u < 4; u++) O[j][u] = 0.f;

    for (int kt = 0; kt < NKT; kt++) {
        if (kt > 0) {
            if (kt + 1 < NKT) { CP_WAIT1(); } else { CP_WAIT0(); }
            __syncthreads();
        }
        uint32_t kvo = AKV0 + (kt & 1) * AKVSZ;
        uint32_t kno = AKN + (kt & 1) * 256;

        // ---- k norms: 4 threads per row (64 rows) ----
        {
            int row = tid >> 2, qtr = tid & 3;
            const __nv_bfloat162* ph =
                (const __nv_bfloat162*)(smc + kvo + row * ASTR + qtr * 32);
            const __nv_bfloat162* pl =
                (const __nv_bfloat162*)(smc + kvo + AMATK + row * ASTR + qtr * 32);
            float s = 0.f;
            #pragma unroll
            for (int d = 0; d < 8; d++) {
                __nv_bfloat162 hh = ph[d], ll = pl[d];
                float v0 = __bfloat162float(hh.x) + __bfloat162float(ll.x);
                float v1 = __bfloat162float(hh.y) + __bfloat162float(ll.y);
                s += v0 * v0 + v1 * v1;
            }
            s += __shfl_xor_sync(0xffffffffu, s, 1);
            s += __shfl_xor_sync(0xffffffffu, s, 2);
            if (!qtr) *(float*)(smc + kno + row * 4) = s;
        }
        __syncthreads();

        // ---- S = Q K^T ----
        float S[8][4];
        #pragma unroll
        for (int j = 0; j < 8; j++)
            #pragma unroll
            for (int u = 0; u < 4; u++) S[j][u] = 0.f;
        #pragma unroll
        for (int s = 0; s < 4; s++) {
            #pragma unroll
            for (int np = 0; np < 4; np++) {
                int browp = np * 16 + (gq >> 1) * 8 + rq;
                uint32_t off = (uint32_t)(browp * ASTR + (s * 16 + (gq & 1) * 8) * 2);
                uint32_t bh[4], bl[4];
                ldsm4(bh, sb + kvo + off);
                ldsm4(bl, sb + kvo + AMATK + off);
                mma16816(S[2 * np],     qfh[s], bh);
                mma16816(S[2 * np],     qfh[s], bl);
                mma16816(S[2 * np],     qfl[s], bh);
                mma16816(S[2 * np + 1], qfh[s], bh + 2);
                mma16816(S[2 * np + 1], qfh[s], bl + 2);
                mma16816(S[2 * np + 1], qfl[s], bh + 2);
            }
        }

        // ---- Yat transform + causal mask + online softmax ----
        bool diag = (kt >= 2 * qt);   // last two tiles intersect diagonal
        int k0g = kt * 64;
        float mx0 = NEGINF, mx1 = NEGINF;
        #pragma unroll
        for (int j = 0; j < 8; j++) {
            int c0 = j * 8 + t * 2;
            float2 knv = *(float2*)(smc + kno + c0 * 4);
            int gc0 = k0g + c0, gc1 = gc0 + 1;
            float sc, den, lg;
            sc = S[j][0] * 0.125f; den = qn0 + knv.x - 2.f * sc + EPSY;
            lg = __fdividef(sc * sc, den);
            if (diag && gc0 > gr0) lg = NEGINF;
            S[j][0] = lg; mx0 = fmaxf(mx0, lg);
            sc = S[j][1] * 0.125f; den = qn0 + knv.y - 2.f * sc + EPSY;
            lg = __fdividef(sc * sc, den);
            if (diag && gc1 > gr0) lg = NEGINF;
            S[j][1] = lg; mx0 = fmaxf(mx0, lg);
            sc = S[j][2] * 0.125f; den = qn1 + knv.x - 2.f * sc + EPSY;
            lg = __fdividef(sc * sc, den);
            if (diag && gc0 > gr1) lg = NEGINF;
            S[j][2] = lg; mx1 = fmaxf(mx1, lg);
            sc = S[j][3] * 0.125f; den = qn1 + knv.y - 2.f * sc + EPSY;
            lg = __fdividef(sc * sc, den);
            if (diag && gc1 > gr1) lg = NEGINF;
            S[j][3] = lg; mx1 = fmaxf(mx1, lg);
        }
        mx0 = fmaxf(mx0, __shfl_xor_sync(0xffffffffu, mx0, 1));
        mx0 = fmaxf(mx0, __shfl_xor_sync(0xffffffffu, mx0, 2));
        mx1 = fmaxf(mx1, __shfl_xor_sync(0xffffffffu, mx1, 1));
        mx1 = fmaxf(mx1, __shfl_xor_sync(0xffffffffu, mx1, 2));
        float mn0 = fmaxf(m0r, mx0), mn1 = fmaxf(m1r, mx1);
        float cor0 = __expf(m0r - mn0), cor1 = __expf(m1r - mn1);
        float rs0 = 0.f, rs1 = 0.f;
        #pragma unroll
        for (int j = 0; j < 8; j++) {
            float p0 = __expf(S[j][0] - mn0); S[j][0] = p0; rs0 += p0;
            float p1 = __expf(S[j][1] - mn0); S[j][1] = p1; rs0 += p1;
            float p2 = __expf(S[j][2] - mn1); S[j][2] = p2; rs1 += p2;
            float p3 = __expf(S[j][3] - mn1); S[j][3] = p3; rs1 += p3;
        }
        rs0 += __shfl_xor_sync(0xffffffffu, rs0, 1);
        rs0 += __shfl_xor_sync(0xffffffffu, rs0, 2);
        rs1 += __shfl_xor_sync(0xffffffffu, rs1, 1);
        rs1 += __shfl_xor_sync(0xffffffffu, rs1, 2);
        l0r = l0r * cor0 + rs0; l1r = l1r * cor1 + rs1;
        m0r = mn0; m1r = mn1;
        #pragma unroll
        for (int j = 0; j < 8; j++) {
            O[j][0] *= cor0; O[j][1] *= cor0;
            O[j][2] *= cor1; O[j][3] *= cor1;
        }

        // ---- O += P @ V ----
        int q4 = lane >> 3;
        #pragma unroll
        for (int s2 = 0; s2 < 4; s2++) {
            uint32_t ah[4], al[4];
            {
                float c0 = S[2 * s2][0], c1 = S[2 * s2][1];
                float c2 = S[2 * s2][2], c3 = S[2 * s2][3];
                float d0 = S[2 * s2 + 1][0], d1 = S[2 * s2 + 1][1];
                float d2 = S[2 * s2 + 1][2], d3 = S[2 * s2 + 1][3];
                ah[0] = packbf(c0, c1); ah[1] = packbf(c2, c3);
                ah[2] = packbf(d0, d1); ah[3] = packbf(d2, d3);
                __nv_bfloat162 h0 = *(__nv_bfloat162*)&ah[0];
                __nv_bfloat162 h1 = *(__nv_bfloat162*)&ah[1];
                __nv_bfloat162 h2 = *(__nv_bfloat162*)&ah[2];
                __nv_bfloat162 h3 = *(__nv_bfloat162*)&ah[3];
                al[0] = packbf(c0 - __bfloat162float(h0.x), c1 - __bfloat162float(h0.y));
                al[1] = packbf(c2 - __bfloat162float(h1.x), c3 - __bfloat162float(h1.y));
                al[2] = packbf(d0 - __bfloat162float(h2.x), d1 - __bfloat162float(h2.y));
                al[3] = packbf(d2 - __bfloat162float(h3.x), d3 - __bfloat162float(h3.y));
            }
            int vrow = s2 * 16 + (q4 & 1) * 8 + (lane & 7);
            #pragma unroll
            for (int g2 = 0; g2 < 4; g2++) {
                uint32_t off = (uint32_t)(vrow * ASTR + (g2 * 16 + (q4 >> 1) * 8) * 2);
                uint32_t bhv[4], blv[4];
                ldsm4t(bhv, sb + kvo + 2 * AMATK + off);
                ldsm4t(blv, sb + kvo + 3 * AMATK + off);
                mma16816(O[2 * g2],     ah, bhv);
                mma16816(O[2 * g2],     ah, blv);
                mma16816(O[2 * g2],     al, bhv);
                mma16816(O[2 * g2 + 1], ah, bhv + 2);
                mma16816(O[2 * g2 + 1], ah, blv + 2);
                mma16816(O[2 * g2 + 1], al, bhv + 2);
            }
        }

        if (kt + 2 < NKT) {
            __syncthreads();
            loadKV(kt + 2, kt & 1);
            CP_COMMIT();
        }
    }

    // ---- normalize + write bf16 hi/lo + per-head row-norm partials ----
    float inv0 = 1.f / l0r, inv1 = 1.f / l1r;
    long row0 = (long)b * T + q0 + wq * 16 + tq;
    float ns0 = 0.f, ns1 = 0.f;
    #pragma unroll
    for (int j2 = 0; j2 < 8; j2++) {
        int col = h * 64 + j2 * 8 + t * 2;
        float v0 = O[j2][0] * inv0, v1 = O[j2][1] * inv0;
        float w0 = O[j2][2] * inv1, w1 = O[j2][3] * inv1;
        ns0 += v0 * v0 + v1 * v1;
        ns1 += w0 * w0 + w1 * w1;
        uint32_t h0 = packbf(v0, v1), h1 = packbf(w0, w1);
        *(uint32_t*)&ohi[row0 * 768 + col] = h0;
        *(uint32_t*)&ohi[(row0 + 8) * 768 + col] = h1;
        __nv_bfloat162 hh0 = *(__nv_bfloat162*)&h0;
        __nv_bfloat162 hh1 = *(__nv_bfloat162*)&h1;
        *(uint32_t*)&olo[row0 * 768 + col] =
            packbf(v0 - __bfloat162float(hh0.x), v1 - __bfloat162float(hh0.y));
        *(uint32_t*)&olo[(row0 + 8) * 768 + col] =
            packbf(w0 - __bfloat162float(hh1.x), w1 - __bfloat162float(hh1.y));
    }
    ns0 += __shfl_xor_sync(0xffffffffu, ns0, 1);
    ns0 += __shfl_xor_sync(0xffffffffu, ns0, 2);
    ns1 += __shfl_xor_sync(0xffffffffu, ns1, 1);
    ns1 += __shfl_xor_sync(0xffffffffu, ns1, 2);
    if (t == 0) {
        anp[row0 * 12 + h] = ns0;
        anp[(row0 + 8) * 12 + h] = ns1;
    }
}

// ================= launch ====================================================
extern "C" void kernel_launch(void* const* d_in, const int* in_sizes, int n_in,
                              void* d_out, int out_size) {
    const float* x          = (const float*)d_in[0];
    // d_in[1] = causal tril mask — applied analytically
    const float* W_attn     = (const float*)d_in[2];
    const float* b_attn     = (const float*)d_in[3];
    const float* alpha_attn = (const float*)d_in[4];
    const float* W_proj     = (const float*)d_in[5];
    const float* b_proj     = (const float*)d_in[6];
    const float* alpha_proj = (const float*)d_in[7];
    float* out = (float*)d_out;

    float *p_xn, *p_an, *p_anp, *p_wn1, *p_wn2;
    __nv_bfloat16 *p_qkvh, *p_qkvl, *p_xhi, *p_xlo, *p_ahi, *p_alo;
    __nv_bfloat16 *p_w1hi, *p_w1lo, *p_w2hi, *p_w2lo;
    cudaGetSymbolAddress((void**)&p_xn, g_xn);
    cudaGetSymbolAddress((void**)&p_an, g_an);
    cudaGetSymbolAddress((void**)&p_anp, g_anp);
    cudaGetSymbolAddress((void**)&p_wn1, g_wn1);
    cudaGetSymbolAddress((void**)&p_wn2, g_wn2);
    cudaGetSymbolAddress((void**)&p_qkvh, g_qkvh);
    cudaGetSymbolAddress((void**)&p_qkvl, g_qkvl);
    cudaGetSymbolAddress((void**)&p_xhi, g_xhi);
    cudaGetSymbolAddress((void**)&p_xlo, g_xlo);
    cudaGetSymbolAddress((void**)&p_ahi, g_ahi);
    cudaGetSymbolAddress((void**)&p_alo, g_alo);
    cudaGetSymbolAddress((void**)&p_w1hi, g_w1hi);
    cudaGetSymbolAddress((void**)&p_w1lo, g_w1lo);
    cudaGetSymbolAddress((void**)&p_w2hi, g_w2hi);
    cudaGetSymbolAddress((void**)&p_w2lo, g_w2lo);

    const int M = 4096, C = 768, F1 = 2304;

    cudaFuncSetAttribute(gemm_mma_k, cudaFuncAttributeMaxDynamicSharedMemorySize, GEMM_SMEM);
    cudaFuncSetAttribute(attn_mma_k, cudaFuncAttributeMaxDynamicSharedMemorySize, ATTN_SMEM);

    // ---- stage 1 prep
    split_norm_k<<<M / 8, 256>>>(x, p_xhi, p_xlo, p_xn, M, C);
    wtrans_split_k<<<dim3(F1 / 32, C / 32), dim3(32, 8)>>>(W_attn, p_w1hi, p_w1lo, C, F1);
    colnorm_k<<<F1 / 256, 256>>>(W_attn, p_wn1, C, F1);

    // ---- stage 1: HMMA Yat-GEMM -> qkv (bf16 hi/lo)
    gemm_mma_k<<<dim3(F1 / 128, M / 128), 256, GEMM_SMEM>>>(
        p_xhi, p_xlo, p_w1hi, p_w1lo, b_attn, p_xn, p_wn1, alpha_attn,
        nullptr, p_qkvh, p_qkvl, M, F1, C, (float)F1);

    // ---- stage 2: HMMA Yat flash attention
    attn_mma_k<<<dim3(12, 4, 8), 256, ATTN_SMEM>>>(
        p_qkvh, p_qkvl, p_ahi, p_alo, p_anp);

    // ---- stage 3 prep + HMMA Yat-GEMM -> out
    anred_k<<<M / 256, 256>>>(p_anp, p_an);
    wtrans_split_k<<<dim3(C / 32, C / 32), dim3(32, 8)>>>(W_proj, p_w2hi, p_w2lo, C, C);
    colnorm_k<<<C / 256, 256>>>(W_proj, p_wn2, C, C);
    gemm_mma_k<<<dim3(C / 128, M / 128), 256, GEMM_SMEM>>>(
        p_ahi, p_alo, p_w2hi, p_w2lo, b_proj, p_an, p_wn2, alpha_proj,
        out, nullptr, nullptr, M, C, C, (float)C);
}

// round 13
// speedup vs baseline: 1.2129x; 1.2129x over previous
#include <cuda_runtime.h>
#include <cuda_bf16.h>
#include <cstdint>
#include <math.h>

#define EPSY (1.0f/137.0f)
#define NEGINF (-3.402823466e38f)

// ================= helpers ===================================================
__device__ __forceinline__ uint32_t smem_u32(const void* p) {
    uint32_t a;
    asm("{ .reg .u64 t; cvta.to.shared.u64 t, %1; cvt.u32.u64 %0, t; }"
        : "=r"(a) : "l"(p));
    return a;
}
__device__ __forceinline__ void cp16(uint32_t s, const void* g) {
    asm volatile("cp.async.cg.shared.global [%0], [%1], 16;" :: "r"(s), "l"(g));
}
#define CP_COMMIT() asm volatile("cp.async.commit_group;" ::: "memory")
#define CP_WAIT1()  asm volatile("cp.async.wait_group 1;" ::: "memory")
#define CP_WAIT0()  asm volatile("cp.async.wait_group 0;" ::: "memory")

__device__ __forceinline__ void ldsm4(uint32_t* r, uint32_t addr) {
    asm volatile("ldmatrix.sync.aligned.m8n8.x4.shared.b16 {%0,%1,%2,%3}, [%4];"
        : "=r"(r[0]), "=r"(r[1]), "=r"(r[2]), "=r"(r[3]) : "r"(addr));
}
__device__ __forceinline__ void ldsm4t(uint32_t* r, uint32_t addr) {
    asm volatile("ldmatrix.sync.aligned.m8n8.x4.trans.shared.b16 {%0,%1,%2,%3}, [%4];"
        : "=r"(r[0]), "=r"(r[1]), "=r"(r[2]), "=r"(r[3]) : "r"(addr));
}
__device__ __forceinline__ void mma16816(float* d, const uint32_t* a, const uint32_t* b) {
    asm volatile(
        "mma.sync.aligned.m16n8k16.row.col.f32.bf16.bf16.f32 "
        "{%0,%1,%2,%3}, {%4,%5,%6,%7}, {%8,%9}, {%0,%1,%2,%3};"
        : "+f"(d[0]), "+f"(d[1]), "+f"(d[2]), "+f"(d[3])
        : "r"(a[0]), "r"(a[1]), "r"(a[2]), "r"(a[3]), "r"(b[0]), "r"(b[1]));
}
__device__ __forceinline__ uint32_t packbf(float a, float b) {
    __nv_bfloat162 p;
    p.x = __float2bfloat16(a);
    p.y = __float2bfloat16(b);
    return *(uint32_t*)&p;
}

// ================= scratch (static device memory) ===========================
__device__ float g_xn[4096];
__device__ float g_an[4096];
__device__ float g_anp[4096 * 12];
__device__ float g_wn1[2304];
__device__ float g_wn2[768];
__device__ __nv_bfloat16 g_qkvh[4096 * 2304], g_qkvl[4096 * 2304];
__device__ __nv_bfloat16 g_xhi[4096 * 768], g_xlo[4096 * 768];
__device__ __nv_bfloat16 g_ahi[4096 * 768], g_alo[4096 * 768];
__device__ __nv_bfloat16 g_w1hi[2304 * 768], g_w1lo[2304 * 768];
__device__ __nv_bfloat16 g_w2hi[768 * 768], g_w2lo[768 * 768];

// ================= prep kernels =============================================
__global__ void split_norm_k(const float* __restrict__ X, __nv_bfloat16* __restrict__ H,
                             __nv_bfloat16* __restrict__ L, float* __restrict__ nrm,
                             int M, int K) {
    int row = blockIdx.x * 8 + (threadIdx.x >> 5);
    int lane = threadIdx.x & 31;
    if (row >= M) return;
    const float* p = X + (long)row * K;
    float s = 0.f;
    for (int k = lane; k < K; k += 32) {
        float v = p[k];
        s = fmaf(v, v, s);
        __nv_bfloat16 hb = __float2bfloat16(v);
        H[(long)row * K + k] = hb;
        L[(long)row * K + k] = __float2bfloat16(v - __bfloat162float(hb));
    }
    #pragma unroll
    for (int o = 16; o; o >>= 1) s += __shfl_xor_sync(0xffffffffu, s, o);
    if (!lane) nrm[row] = s;
}

// coalesced column sum-of-squares: 32 cols x 8-way k split per block
__global__ void colnorm_k(const float* __restrict__ W, float* __restrict__ o, int K, int N) {
    __shared__ float red[8][33];
    int n = blockIdx.x * 32 + threadIdx.x;
    float s = 0.f;
    for (int k = threadIdx.y; k < K; k += 8) {
        float v = W[(long)k * N + n];
        s = fmaf(v, v, s);
    }
    red[threadIdx.y][threadIdx.x] = s;
    __syncthreads();
    if (threadIdx.y == 0) {
        float t = 0.f;
        #pragma unroll
        for (int i = 0; i < 8; i++) t += red[i][threadIdx.x];
        o[n] = t;
    }
}

__global__ void anred_k(const float* __restrict__ part, float* __restrict__ o) {
    int r = blockIdx.x * 256 + threadIdx.x;
    float s = 0.f;
    #pragma unroll
    for (int h = 0; h < 12; h++) s += part[r * 12 + h];
    o[r] = s;
}

__global__ void wtrans_split_k(const float* __restrict__ W, __nv_bfloat16* __restrict__ Th,
                               __nv_bfloat16* __restrict__ Tl, int K, int N) {
    __shared__ float t[32][33];
    int n0 = blockIdx.x * 32, k0 = blockIdx.y * 32;
    int tx = threadIdx.x, ty = threadIdx.y;  // (32, 8)
    #pragma unroll
    for (int j = 0; j < 32; j += 8)
        t[ty + j][tx] = W[(long)(k0 + ty + j) * N + n0 + tx];
    __syncthreads();
    #pragma unroll
    for (int j = 0; j < 32; j += 8) {
        float v = t[tx][ty + j];
        __nv_bfloat16 hb = __float2bfloat16(v);
        Th[(long)(n0 + ty + j) * K + k0 + tx] = hb;
        Tl[(long)(n0 + ty + j) * K + k0 + tx] = __float2bfloat16(v - __bfloat162float(hb));
    }
}

// ================= HMMA Yat-GEMM (warp tile 64x64, 128 threads) =============
#define BK 32
#define STR 80                    // 32 bf16 = 64B + 16B pad
#define MAT_BYTES (128 * STR)     // 10240
#define BUF_BYTES (4 * MAT_BYTES) // 40960
#define GEMM_SMEM (2 * BUF_BYTES) // 81920

__global__ __launch_bounds__(128, 2)
void gemm_mma_k(const __nv_bfloat16* __restrict__ Ah, const __nv_bfloat16* __restrict__ Al,
                const __nv_bfloat16* __restrict__ Bh, const __nv_bfloat16* __restrict__ Bl,
                const float* __restrict__ bias, const float* __restrict__ rn,
                const float* __restrict__ cn, const float* __restrict__ alphaPtr,
                float* __restrict__ Cout,
                __nv_bfloat16* __restrict__ Ohi, __nv_bfloat16* __restrict__ Olo,
                int M, int N, int K, float baseF) {
    extern __shared__ char smc[];
    uint32_t sb = smem_u32(smc);
    int tid = threadIdx.x, wid = tid >> 5, lane = tid & 31;
    int M0 = blockIdx.y * 128, N0 = blockIdx.x * 128;
    int wm = wid & 1, wn = wid >> 1;   // warp tile: 64(m) x 64(n)

    float acc[4][8][4];
    #pragma unroll
    for (int i = 0; i < 4; i++)
        #pragma unroll
        for (int j = 0; j < 8; j++)
            #pragma unroll
            for (int u = 0; u < 4; u++) acc[i][j][u] = 0.f;

    const int NCH = K / BK;

    auto load_chunk = [&](int c, int buf) {
        int k0 = c * BK;
        uint32_t base = sb + buf * BUF_BYTES;
        #pragma unroll
        for (int l = 0; l < 4; l++) {
            int f = tid + l * 128;      // 0..511
            int row = f >> 2, seg = f & 3;
            uint32_t so = row * STR + seg * 16;
            long ga = (long)(M0 + row) * K + k0 + seg * 8;
            long gb = (long)(N0 + row) * K + k0 + seg * 8;
            cp16(base + so,                 Ah + ga);
            cp16(base + MAT_BYTES + so,     Al + ga);
            cp16(base + 2 * MAT_BYTES + so, Bh + gb);
            cp16(base + 3 * MAT_BYTES + so, Bl + gb);
        }
    };

    load_chunk(0, 0); CP_COMMIT();
    load_chunk(1, 1); CP_COMMIT();

    int gq = lane >> 3, rq = lane & 7;
    int arow = wm * 64 + (gq & 1) * 8 + rq;
    int acol8 = (gq >> 1) * 8;
    int brow0 = wn * 64 + (gq >> 1) * 8 + rq;
    int bcol8 = (gq & 1) * 8;

    for (int c = 0; c < NCH; c++) {
        if (c + 1 < NCH) { CP_WAIT1(); } else { CP_WAIT0(); }
        __syncthreads();
        uint32_t base = sb + (c & 1) * BUF_BYTES;
        uint32_t bAh = base, bAl = base + MAT_BYTES;
        uint32_t bBh = base + 2 * MAT_BYTES, bBl = base + 3 * MAT_BYTES;

        #pragma unroll
        for (int ks = 0; ks < BK / 16; ks++) {
            int kc = ks * 16;
            uint32_t ah[4][4], al[4][4], bh[8][2], bl[8][2];
            #pragma unroll
            for (int i = 0; i < 4; i++) {
                uint32_t off = (uint32_t)((arow + i * 16) * STR + (kc + acol8) * 2);
                ldsm4(ah[i], bAh + off);
                ldsm4(al[i], bAl + off);
            }
            #pragma unroll
            for (int jb = 0; jb < 4; jb++) {
                uint32_t off = (uint32_t)((brow0 + jb * 16) * STR + (kc + bcol8) * 2);
                uint32_t r[4];
                ldsm4(r, bBh + off);
                bh[jb * 2][0] = r[0]; bh[jb * 2][1] = r[1];
                bh[jb * 2 + 1][0] = r[2]; bh[jb * 2 + 1][1] = r[3];
                ldsm4(r, bBl + off);
                bl[jb * 2][0] = r[0]; bl[jb * 2][1] = r[1];
                bl[jb * 2 + 1][0] = r[2]; bl[jb * 2 + 1][1] = r[3];
            }
            #pragma unroll
            for (int i = 0; i < 4; i++)
                #pragma unroll
                for (int j = 0; j < 8; j++) {
                    mma16816(acc[i][j], ah[i], bh[j]);
                    mma16816(acc[i][j], ah[i], bl[j]);
                    mma16816(acc[i][j], al[i], bh[j]);
                }
        }
        if (c + 2 < NCH) {
            __syncthreads();
            load_chunk(c + 2, c & 1);
            CP_COMMIT();
        }
    }

    float alpha = __ldg(alphaPtr);
    float scaleF = powf(sqrtf(baseF) / logf(1.0f + baseF), alpha);
    int tq = lane >> 2, tr = lane & 3;
    #pragma unroll
    for (int i = 0; i < 4; i++) {
        int m0 = M0 + wm * 64 + i * 16 + tq;
        float rn0 = __ldg(&rn[m0]);
        float rn1 = __ldg(&rn[m0 + 8]);
        #pragma unroll
        for (int j = 0; j < 8; j++) {
            int n0 = N0 + wn * 64 + j * 8 + tr * 2;
            float cn0 = __ldg(&cn[n0]), cn1 = __ldg(&cn[n0 + 1]);
            float bb0 = __ldg(&bias[n0]), bb1 = __ldg(&bias[n0 + 1]);
            float c0 = acc[i][j][0], c1 = acc[i][j][1];
            float c2 = acc[i][j][2], c3 = acc[i][j][3];
            float2 r0, r1;
            r0.x = (c0 * c0 / (rn0 + cn0 - 2.f * c0 + EPSY) + bb0) * scaleF;
            r0.y = (c1 * c1 / (rn0 + cn1 - 2.f * c1 + EPSY) + bb1) * scaleF;
            r1.x = (c2 * c2 / (rn1 + cn0 - 2.f * c2 + EPSY) + bb0) * scaleF;
            r1.y = (c3 * c3 / (rn1 + cn1 - 2.f * c3 + EPSY) + bb1) * scaleF;
            if (Cout) {
                *(float2*)&Cout[(long)m0 * N + n0] = r0;
                *(float2*)&Cout[(long)(m0 + 8) * N + n0] = r1;
            }
            if (Ohi) {
                uint32_t h0 = packbf(r0.x, r0.y);
                uint32_t h1 = packbf(r1.x, r1.y);
                *(uint32_t*)&Ohi[(long)m0 * N + n0] = h0;
                *(uint32_t*)&Ohi[(long)(m0 + 8) * N + n0] = h1;
                __nv_bfloat162 hh0 = *(__nv_bfloat162*)&h0;
                __nv_bfloat162 hh1 = *(__nv_bfloat162*)&h1;
                uint32_t l0 = packbf(r0.x - __bfloat162float(hh0.x),
                                     r0.y - __bfloat162float(hh0.y));
                uint32_t l1 = packbf(r1.x - __bfloat162float(hh1.x),
                                     r1.y - __bfloat162float(hh1.y));
                *(uint32_t*)&Olo[(long)m0 * N + n0] = l0;
                *(uint32_t*)&Olo[(long)(m0 + 8) * N + n0] = l1;
            }
        }
    }
}

// ================= HMMA Yat flash attention (R9 config: KV 128, occ 1) ======
#define ASTR 144
#define AMAT (128 * ASTR)
#define AQOFF 0
#define AKV0 (2 * AMAT)
#define AKVSZ (4 * AMAT)
#define AKN (AKV0 + 2 * AKVSZ)
#define ATTN_SMEM (AKN + 2 * 512)

__global__ __launch_bounds__(256, 1)
void attn_mma_k(const __nv_bfloat16* __restrict__ qh,
                const __nv_bfloat16* __restrict__ ql,
                __nv_bfloat16* __restrict__ ohi, __nv_bfloat16* __restrict__ olo,
                float* __restrict__ anp) {
    extern __shared__ char smc[];
    uint32_t sb = smem_u32(smc);
    int tid = threadIdx.x, wq = tid >> 5, lane = tid & 31;
    int h = blockIdx.x, b = blockIdx.y;
    int qt = 7 - blockIdx.z;          // longest CTAs first
    int q0 = qt * 128;
    const int T = 1024, C3 = 2304;
    long rbase = (long)b * T * C3;
    int qcol = h * 64, kcol = 768 + h * 64, vcol = 1536 + h * 64;

    auto loadQ = [&]() {
        #pragma unroll
        for (int l = 0; l < 4; l++) {
            int f = tid + l * 256;
            int row = f >> 3, seg = f & 7;
            long g = rbase + (long)(q0 + row) * C3 + qcol + seg * 8;
            uint32_t so = row * ASTR + seg * 16;
            cp16(sb + AQOFF + so, qh + g);
            cp16(sb + AQOFF + AMAT + so, ql + g);
        }
    };
    auto loadKV = [&](int kt, int buf) {
        int k0 = kt * 128;
        uint32_t base = sb + AKV0 + buf * AKVSZ;
        #pragma unroll
        for (int l = 0; l < 4; l++) {
            int f = tid + l * 256;
            int row = f >> 3, seg = f & 7;
            uint32_t so = row * ASTR + seg * 16;
            long gk = rbase + (long)(k0 + row) * C3 + kcol + seg * 8;
            long gv = rbase + (long)(k0 + row) * C3 + vcol + seg * 8;
            cp16(base + so,            qh + gk);
            cp16(base + AMAT + so,     ql + gk);
            cp16(base + 2 * AMAT + so, qh + gv);
            cp16(base + 3 * AMAT + so, ql + gv);
        }
    };

    loadQ(); loadKV(0, 0); CP_COMMIT();
    if (qt >= 1) { loadKV(1, 1); CP_COMMIT(); CP_WAIT1(); } else { CP_WAIT0(); }
    __syncthreads();

    int gq = lane >> 3, rq = lane & 7;
    int arow = wq * 16 + (gq & 1) * 8 + rq;
    int acol8 = (gq >> 1) * 8;
    uint32_t qfh[4][4], qfl[4][4];
    #pragma unroll
    for (int s = 0; s < 4; s++) {
        uint32_t off = (uint32_t)(arow * ASTR + (s * 16 + acol8) * 2);
        ldsm4(qfh[s], sb + AQOFF + off);
        ldsm4(qfl[s], sb + AQOFF + AMAT + off);
    }
    float qn0 = 0.f, qn1 = 0.f;
    #pragma unroll
    for (int s = 0; s < 4; s++)
        #pragma unroll
        for (int r = 0; r < 4; r++) {
            __nv_bfloat162 hh = *(__nv_bfloat162*)&qfh[s][r];
            __nv_bfloat162 ll = *(__nv_bfloat162*)&qfl[s][r];
            float v0 = __bfloat162float(hh.x) + __bfloat162float(ll.x);
            float v1 = __bfloat162float(hh.y) + __bfloat162float(ll.y);
            float ss = v0 * v0 + v1 * v1;
            if ((r & 1) == 0) qn0 += ss; else qn1 += ss;
        }
    qn0 += __shfl_xor_sync(0xffffffffu, qn0, 1);
    qn0 += __shfl_xor_sync(0xffffffffu, qn0, 2);
    qn1 += __shfl_xor_sync(0xffffffffu, qn1, 1);
    qn1 += __shfl_xor_sync(0xffffffffu, qn1, 2);

    int tq = lane >> 2, t = lane & 3;
    int gr0 = q0 + wq * 16 + tq, gr1 = gr0 + 8;
    float m0r = NEGINF, m1r = NEGINF, l0r = 0.f, l1r = 0.f;
    float O[8][4];
    #pragma unroll
    for (int j = 0; j < 8; j++)
        #pragma unroll
        for (int u = 0; u < 4; u++) O[j][u] = 0.f;

    for (int kt = 0; kt <= qt; kt++) {
        if (kt > 0) {
            if (kt + 1 <= qt) { CP_WAIT1(); } else { CP_WAIT0(); }
            __syncthreads();
        }
        uint32_t kvo = AKV0 + (kt & 1) * AKVSZ;
        uint32_t kno = AKN + (kt & 1) * 512;

        {
            int row = tid >> 1, half = tid & 1;
            const __nv_bfloat162* ph =
                (const __nv_bfloat162*)(smc + kvo + row * ASTR + half * 64);
            const __nv_bfloat162* pl =
                (const __nv_bfloat162*)(smc + kvo + AMAT + row * ASTR + half * 64);
            float s = 0.f;
            #pragma unroll
            for (int d = 0; d < 16; d++) {
                __nv_bfloat162 hh = ph[d], ll = pl[d];
                float v0 = __bfloat162float(hh.x) + __bfloat162float(ll.x);
                float v1 = __bfloat162float(hh.y) + __bfloat162float(ll.y);
                s += v0 * v0 + v1 * v1;
            }
            s += __shfl_xor_sync(0xffffffffu, s, 1);
            if (!half) *(float*)(smc + kno + row * 4) = s;
        }
        __syncthreads();

        float S[16][4];
        #pragma unroll
        for (int j = 0; j < 16; j++)
            #pragma unroll
            for (int u = 0; u < 4; u++) S[j][u] = 0.f;
        #pragma unroll
        for (int s = 0; s < 4; s++) {
            #pragma unroll
            for (int np = 0; np < 8; np++) {
                int browp = np * 16 + (gq >> 1) * 8 + rq;
                uint32_t off = (uint32_t)(browp * ASTR + (s * 16 + (gq & 1) * 8) * 2);
                uint32_t bh[4], bl[4];
                ldsm4(bh, sb + kvo + off);
                ldsm4(bl, sb + kvo + AMAT + off);
                mma16816(S[2 * np],     qfh[s], bh);
                mma16816(S[2 * np],     qfh[s], bl);
                mma16816(S[2 * np],     qfl[s], bh);
                mma16816(S[2 * np + 1], qfh[s], bh + 2);
                mma16816(S[2 * np + 1], qfh[s], bl + 2);
                mma16816(S[2 * np + 1], qfl[s], bh + 2);
            }
        }

        bool diag = (kt == qt);
        int k0g = kt * 128;
        float mx0 = NEGINF, mx1 = NEGINF;
        #pragma unroll
        for (int j = 0; j < 16; j++) {
            int c0 = j * 8 + t * 2;
            float2 knv = *(float2*)(smc + kno + c0 * 4);
            int gc0 = k0g + c0, gc1 = gc0 + 1;
            float sc, den, lg;
            sc = S[j][0] * 0.125f; den = qn0 + knv.x - 2.f * sc + EPSY;
            lg = __fdividef(sc * sc, den);
            if (diag && gc0 > gr0) lg = NEGINF;
            S[j][0] = lg; mx0 = fmaxf(mx0, lg);
            sc = S[j][1] * 0.125f; den = qn0 + knv.y - 2.f * sc + EPSY;
            lg = __fdividef(sc * sc, den);
            if (diag && gc1 > gr0) lg = NEGINF;
            S[j][1] = lg; mx0 = fmaxf(mx0, lg);
            sc = S[j][2] * 0.125f; den = qn1 + knv.x - 2.f * sc + EPSY;
            lg = __fdividef(sc * sc, den);
            if (diag && gc0 > gr1) lg = NEGINF;
            S[j][2] = lg; mx1 = fmaxf(mx1, lg);
            sc = S[j][3] * 0.125f; den = qn1 + knv.y - 2.f * sc + EPSY;
            lg = __fdividef(sc * sc, den);
            if (diag && gc1 > gr1) lg = NEGINF;
            S[j][3] = lg; mx1 = fmaxf(mx1, lg);
        }
        mx0 = fmaxf(mx0, __shfl_xor_sync(0xffffffffu, mx0, 1));
        mx0 = fmaxf(mx0, __shfl_xor_sync(0xffffffffu, mx0, 2));
        mx1 = fmaxf(mx1, __shfl_xor_sync(0xffffffffu, mx1, 1));
        mx1 = fmaxf(mx1, __shfl_xor_sync(0xffffffffu, mx1, 2));
        float mn0 = fmaxf(m0r, mx0), mn1 = fmaxf(m1r, mx1);
        float cor0 = __expf(m0r - mn0), cor1 = __expf(m1r - mn1);
        float rs0 = 0.f, rs1 = 0.f;
        #pragma unroll
        for (int j = 0; j < 16; j++) {
            float p0 = __expf(S[j][0] - mn0); S[j][0] = p0; rs0 += p0;
            float p1 = __expf(S[j][1] - mn0); S[j][1] = p1; rs0 += p1;
            float p2 = __expf(S[j][2] - mn1); S[j][2] = p2; rs1 += p2;
            float p3 = __expf(S[j][3] - mn1); S[j][3] = p3; rs1 += p3;
        }
        rs0 += __shfl_xor_sync(0xffffffffu, rs0, 1);
        rs0 += __shfl_xor_sync(0xffffffffu, rs0, 2);
        rs1 += __shfl_xor_sync(0xffffffffu, rs1, 1);
        rs1 += __shfl_xor_sync(0xffffffffu, rs1, 2);
        l0r = l0r * cor0 + rs0; l1r = l1r * cor1 + rs1;
        m0r = mn0; m1r = mn1;
        #pragma unroll
        for (int j = 0; j < 8; j++) {
            O[j][0] *= cor0; O[j][1] *= cor0;
            O[j][2] *= cor1; O[j][3] *= cor1;
        }

        int q4 = lane >> 3;
        #pragma unroll
        for (int s2 = 0; s2 < 8; s2++) {
            uint32_t ah[4], al[4];
            {
                float c0 = S[2 * s2][0], c1 = S[2 * s2][1];
                float c2 = S[2 * s2][2], c3 = S[2 * s2][3];
                float d0 = S[2 * s2 + 1][0], d1 = S[2 * s2 + 1][1];
                float d2 = S[2 * s2 + 1][2], d3 = S[2 * s2 + 1][3];
                ah[0] = packbf(c0, c1); ah[1] = packbf(c2, c3);
                ah[2] = packbf(d0, d1); ah[3] = packbf(d2, d3);
                __nv_bfloat162 h0 = *(__nv_bfloat162*)&ah[0];
                __nv_bfloat162 h1 = *(__nv_bfloat162*)&ah[1];
                __nv_bfloat162 h2 = *(__nv_bfloat162*)&ah[2];
                __nv_bfloat162 h3 = *(__nv_bfloat162*)&ah[3];
                al[0] = packbf(c0 - __bfloat162float(h0.x), c1 - __bfloat162float(h0.y));
                al[1] = packbf(c2 - __bfloat162float(h1.x), c3 - __bfloat162float(h1.y));
                al[2] = packbf(d0 - __bfloat162float(h2.x), d1 - __bfloat162float(h2.y));
                al[3] = packbf(d2 - __bfloat162float(h3.x), d3 - __bfloat162float(h3.y));
            }
            int vrow = s2 * 16 + (q4 & 1) * 8 + (lane & 7);
            #pragma unroll
            for (int g2 = 0; g2 < 4; g2++) {
                uint32_t off = (uint32_t)(vrow * ASTR + (g2 * 16 + (q4 >> 1) * 8) * 2);
                uint32_t bhv[4], blv[4];
                ldsm4t(bhv, sb + kvo + 2 * AMAT + off);
                ldsm4t(blv, sb + kvo + 3 * AMAT + off);
                mma16816(O[2 * g2],     ah, bhv);
                mma16816(O[2 * g2],     ah, blv);
                mma16816(O[2 * g2],     al, bhv);
                mma16816(O[2 * g2 + 1], ah, bhv + 2);
                mma16816(O[2 * g2 + 1], ah, blv + 2);
                mma16816(O[2 * g2 + 1], al, bhv + 2);
            }
        }

        if (kt + 2 <= qt) {
            __syncthreads();
            loadKV(kt + 2, kt & 1);
            CP_COMMIT();
        }
    }

    float inv0 = 1.f / l0r, inv1 = 1.f / l1r;
    long row0 = (long)b * T + q0 + wq * 16 + tq;
    float ns0 = 0.f, ns1 = 0.f;
    #pragma unroll
    for (int j2 = 0; j2 < 8; j2++) {
        int col = h * 64 + j2 * 8 + t * 2;
        float v0 = O[j2][0] * inv0, v1 = O[j2][1] * inv0;
        float w0 = O[j2][2] * inv1, w1 = O[j2][3] * inv1;
        ns0 += v0 * v0 + v1 * v1;
        ns1 += w0 * w0 + w1 * w1;
        uint32_t h0 = packbf(v0, v1), h1 = packbf(w0, w1);
        *(uint32_t*)&ohi[row0 * 768 + col] = h0;
        *(uint32_t*)&ohi[(row0 + 8) * 768 + col] = h1;
        __nv_bfloat162 hh0 = *(__nv_bfloat162*)&h0;
        __nv_bfloat162 hh1 = *(__nv_bfloat162*)&h1;
        *(uint32_t*)&olo[row0 * 768 + col] =
            packbf(v0 - __bfloat162float(hh0.x), v1 - __bfloat162float(hh0.y));
        *(uint32_t*)&olo[(row0 + 8) * 768 + col] =
            packbf(w0 - __bfloat162float(hh1.x), w1 - __bfloat162float(hh1.y));
    }
    ns0 += __shfl_xor_sync(0xffffffffu, ns0, 1);
    ns0 += __shfl_xor_sync(0xffffffffu, ns0, 2);
    ns1 += __shfl_xor_sync(0xffffffffu, ns1, 1);
    ns1 += __shfl_xor_sync(0xffffffffu, ns1, 2);
    if (t == 0) {
        anp[row0 * 12 + h] = ns0;
        anp[(row0 + 8) * 12 + h] = ns1;
    }
}

// ================= launch ====================================================
extern "C" void kernel_launch(void* const* d_in, const int* in_sizes, int n_in,
                              void* d_out, int out_size) {
    const float* x          = (const float*)d_in[0];
    // d_in[1] = causal tril mask — applied analytically
    const float* W_attn     = (const float*)d_in[2];
    const float* b_attn     = (const float*)d_in[3];
    const float* alpha_attn = (const float*)d_in[4];
    const float* W_proj     = (const float*)d_in[5];
    const float* b_proj     = (const float*)d_in[6];
    const float* alpha_proj = (const float*)d_in[7];
    float* out = (float*)d_out;

    float *p_xn, *p_an, *p_anp, *p_wn1, *p_wn2;
    __nv_bfloat16 *p_qkvh, *p_qkvl, *p_xhi, *p_xlo, *p_ahi, *p_alo;
    __nv_bfloat16 *p_w1hi, *p_w1lo, *p_w2hi, *p_w2lo;
    cudaGetSymbolAddress((void**)&p_xn, g_xn);
    cudaGetSymbolAddress((void**)&p_an, g_an);
    cudaGetSymbolAddress((void**)&p_anp, g_anp);
    cudaGetSymbolAddress((void**)&p_wn1, g_wn1);
    cudaGetSymbolAddress((void**)&p_wn2, g_wn2);
    cudaGetSymbolAddress((void**)&p_qkvh, g_qkvh);
    cudaGetSymbolAddress((void**)&p_qkvl, g_qkvl);
    cudaGetSymbolAddress((void**)&p_xhi, g_xhi);
    cudaGetSymbolAddress((void**)&p_xlo, g_xlo);
    cudaGetSymbolAddress((void**)&p_ahi, g_ahi);
    cudaGetSymbolAddress((void**)&p_alo, g_alo);
    cudaGetSymbolAddress((void**)&p_w1hi, g_w1hi);
    cudaGetSymbolAddress((void**)&p_w1lo, g_w1lo);
    cudaGetSymbolAddress((void**)&p_w2hi, g_w2hi);
    cudaGetSymbolAddress((void**)&p_w2lo, g_w2lo);

    const int M = 4096, C = 768, F1 = 2304;

    cudaFuncSetAttribute(gemm_mma_k, cudaFuncAttributeMaxDynamicSharedMemorySize, GEMM_SMEM);
    cudaFuncSetAttribute(attn_mma_k, cudaFuncAttributeMaxDynamicSharedMemorySize, ATTN_SMEM);

    // ---- stage 1 prep
    split_norm_k<<<M / 8, 256>>>(x, p_xhi, p_xlo, p_xn, M, C);
    wtrans_split_k<<<dim3(F1 / 32, C / 32), dim3(32, 8)>>>(W_attn, p_w1hi, p_w1lo, C, F1);
    colnorm_k<<<F1 / 32, dim3(32, 8)>>>(W_attn, p_wn1, C, F1);

    // ---- stage 1: HMMA Yat-GEMM -> qkv (bf16 hi/lo)
    gemm_mma_k<<<dim3(F1 / 128, M / 128), 128, GEMM_SMEM>>>(
        p_xhi, p_xlo, p_w1hi, p_w1lo, b_attn, p_xn, p_wn1, alpha_attn,
        nullptr, p_qkvh, p_qkvl, M, F1, C, (float)F1);

    // ---- stage 2: HMMA Yat flash attention
    attn_mma_k<<<dim3(12, 4, 8), 256, ATTN_SMEM>>>(
        p_qkvh, p_qkvl, p_ahi, p_alo, p_anp);

    // ---- stage 3 prep + HMMA Yat-GEMM -> out
    anred_k<<<M / 256, 256>>>(p_anp, p_an);
    wtrans_split_k<<<dim3(C / 32, C / 32), dim3(32, 8)>>>(W_proj, p_w2hi, p_w2lo, C, C);
    colnorm_k<<<C / 32, dim3(32, 8)>>>(W_proj, p_wn2, C, C);
    gemm_mma_k<<<dim3(C / 128, M / 128), 128, GEMM_SMEM>>>(
        p_ahi, p_alo, p_w2hi, p_w2lo, b_proj, p_an, p_wn2, alpha_proj,
        out, nullptr, nullptr, M, C, C, (float)C);
}